// round 6
// baseline (speedup 1.0000x reference)
#include <cuda_runtime.h>
#include <cuda_bf16.h>
#include <cstdint>

#define Bb   4
#define Tt   1024
#define EMBD 1024
#define Hh   16
#define HEAD 64
#define BTR  (Bb * Tt)
#define NEG_BIG (-1e30f)

// ---------------------------------------------------------------------------
// bf16 hi/lo scratch regions (bytes). Each matrix region = hi(8MB) + lo(8MB).
// ---------------------------------------------------------------------------
#define MB1 (1024ull * 1024ull)
#define R_X   (0ull   * MB1)
#define R_C   (16ull  * MB1)
#define R_WQ  (32ull  * MB1)
#define R_WK  (48ull  * MB1)
#define R_WV  (64ull  * MB1)
#define R_WO  (80ull  * MB1)
#define R_Q   (96ull  * MB1)
#define R_K   (112ull * MB1)
#define R_V   (128ull * MB1)
#define R_O   (144ull * MB1)
#define R_M   (160ull * MB1)
#define SCR_SZ (164ull * MB1)
#define LO_ELEMS (4ull * MB1)     // bf16 elems between hi and lo matrices

static __device__ __align__(16) uint8_t g_scr[SCR_SZ];

// ===========================================================================
// helpers
// ===========================================================================
__device__ __forceinline__ uint32_t smem_u32(const void* p) {
    uint32_t a;
    asm("{ .reg .u64 t; cvta.to.shared.u64 t, %1; cvt.u32.u64 %0, t; }" : "=r"(a) : "l"(p));
    return a;
}
__device__ __forceinline__ void ldsm4(uint32_t addr, uint32_t& r0, uint32_t& r1,
                                      uint32_t& r2, uint32_t& r3) {
    asm volatile("ldmatrix.sync.aligned.m8n8.x4.shared.b16 {%0,%1,%2,%3}, [%4];"
                 : "=r"(r0), "=r"(r1), "=r"(r2), "=r"(r3) : "r"(addr));
}
__device__ __forceinline__ void ldsm4t(uint32_t addr, uint32_t& r0, uint32_t& r1,
                                       uint32_t& r2, uint32_t& r3) {
    asm volatile("ldmatrix.sync.aligned.m8n8.x4.trans.shared.b16 {%0,%1,%2,%3}, [%4];"
                 : "=r"(r0), "=r"(r1), "=r"(r2), "=r"(r3) : "r"(addr));
}
__device__ __forceinline__ void mma_bf16(float (&d)[4], const uint32_t (&a)[4],
                                         uint32_t b0, uint32_t b1) {
    asm volatile("mma.sync.aligned.m16n8k16.row.col.f32.bf16.bf16.f32 "
                 "{%0,%1,%2,%3},{%4,%5,%6,%7},{%8,%9},{%0,%1,%2,%3};"
                 : "+f"(d[0]), "+f"(d[1]), "+f"(d[2]), "+f"(d[3])
                 : "r"(a[0]), "r"(a[1]), "r"(a[2]), "r"(a[3]), "r"(b0), "r"(b1));
}
__device__ __forceinline__ void cvt_hilo(float4 v, uint2& hi, uint2& lo) {
    __nv_bfloat162 h0 = __floats2bfloat162_rn(v.x, v.y);
    __nv_bfloat162 h1 = __floats2bfloat162_rn(v.z, v.w);
    float rx = v.x - __bfloat162float(h0.x);
    float ry = v.y - __bfloat162float(h0.y);
    float rz = v.z - __bfloat162float(h1.x);
    float rw = v.w - __bfloat162float(h1.y);
    __nv_bfloat162 l0 = __floats2bfloat162_rn(rx, ry);
    __nv_bfloat162 l1 = __floats2bfloat162_rn(rz, rw);
    hi = make_uint2(*(uint32_t*)&h0, *(uint32_t*)&h1);
    lo = make_uint2(*(uint32_t*)&l0, *(uint32_t*)&l1);
}
__device__ __forceinline__ void pack2(float x, float y, uint32_t& h, uint32_t& l) {
    __nv_bfloat162 hh = __floats2bfloat162_rn(x, y);
    float rx = x - __bfloat162float(hh.x);
    float ry = y - __bfloat162float(hh.y);
    __nv_bfloat162 ll = __floats2bfloat162_rn(rx, ry);
    h = *(uint32_t*)&hh;
    l = *(uint32_t*)&ll;
}

// ===========================================================================
// prep: fp32 inputs -> bf16 hi/lo matrices; mask int32 -> u8
// ===========================================================================
__global__ void __launch_bounds__(256)
prep_all(const float* __restrict__ x, const float* __restrict__ ctx,
         const float* __restrict__ wq, const float* __restrict__ wk,
         const float* __restrict__ wv, const float* __restrict__ wo)
{
    const int z = blockIdx.z;
    const float* srcs[6] = {x, ctx, wq, wk, wv, wo};
    const size_t offs[6] = {R_X, R_C, R_WQ, R_WK, R_WV, R_WO};
    const float4* s = (const float4*)srcs[z];
    uint2* h = (uint2*)(g_scr + offs[z]);
    uint2* l = (uint2*)(g_scr + offs[z] + 8ull * MB1);
    size_t i = (size_t)blockIdx.x * 256 + threadIdx.x;   // 1M float4 / matrix
    uint2 hh, ll;
    cvt_hilo(s[i], hh, ll);
    h[i] = hh;
    l[i] = ll;
}

__global__ void __launch_bounds__(256)
prep_mask(const int* __restrict__ m)
{
    size_t i = (size_t)blockIdx.x * 256 + threadIdx.x;   // 1M int4
    int4 v = ((const int4*)m)[i];
    uchar4 o;
    o.x = v.x ? 1 : 0; o.y = v.y ? 1 : 0; o.z = v.z ? 1 : 0; o.w = v.w ? 1 : 0;
    ((uchar4*)(g_scr + R_M))[i] = o;
}

// ===========================================================================
// NT GEMM on bf16 hi/lo inputs: C = A * B^T. 128x128 block, BK=32, 8 warps,
// bf16x3. WMODE 0: fp32 C out. WMODE 1: hi/lo bf16 C out.
// ===========================================================================
#define STR_K  40
#define A_HI_O 0
#define A_LO_O 10240
#define B_HI_O 20480
#define B_LO_O 30720
#define STAGE_NT 40960

template <int WMODE>
__device__ __forceinline__ void nt_body_bf(
    const __nv_bfloat16* __restrict__ Ahi, const __nv_bfloat16* __restrict__ Alo,
    const __nv_bfloat16* __restrict__ Bhi, const __nv_bfloat16* __restrict__ Blo,
    float* __restrict__ Cf, __nv_bfloat16* __restrict__ Chi,
    __nv_bfloat16* __restrict__ Clo, char* sm)
{
    const int tid = threadIdx.x, lane = tid & 31, wid = tid >> 5;
    const int m0 = blockIdx.y * 128;
    const int n0 = blockIdx.x * 128;
    const int NC = EMBD / 32;

    float acc[4][4][4] = {};
    uint4 ua[2], ual[2], ub[2], ubl[2];

    // prologue: stage 0
    #pragma unroll
    for (int i = 0; i < 2; i++) {
        int seg = tid + i * 256, row = seg >> 2, c8 = (seg & 3) << 3;
        ua[i]  = *(const uint4*)&Ahi[(size_t)(m0 + row) * EMBD + c8];
        ual[i] = *(const uint4*)&Alo[(size_t)(m0 + row) * EMBD + c8];
        ub[i]  = *(const uint4*)&Bhi[(size_t)(n0 + row) * EMBD + c8];
        ubl[i] = *(const uint4*)&Blo[(size_t)(n0 + row) * EMBD + c8];
    }
    #pragma unroll
    for (int i = 0; i < 2; i++) {
        int seg = tid + i * 256, row = seg >> 2, c8 = (seg & 3) << 3;
        uint32_t off = (uint32_t)(row * STR_K + c8) * 2;
        *(uint4*)(sm + A_HI_O + off) = ua[i];
        *(uint4*)(sm + A_LO_O + off) = ual[i];
        *(uint4*)(sm + B_HI_O + off) = ub[i];
        *(uint4*)(sm + B_LO_O + off) = ubl[i];
    }
    __syncthreads();

    const int wm = wid >> 2, wn = wid & 3;
    const int arow = lane & 15, acol8 = (lane >> 4) << 3;
    const int brow = (lane & 7) + ((lane >> 4) << 3), bcol8 = ((lane >> 3) & 1) << 3;
    const uint32_t sb0 = smem_u32(sm);

    for (int c = 0; c < NC; c++) {
        if (c + 1 < NC) {
            int k0n = (c + 1) * 32;
            #pragma unroll
            for (int i = 0; i < 2; i++) {
                int seg = tid + i * 256, row = seg >> 2, c8 = (seg & 3) << 3;
                ua[i]  = *(const uint4*)&Ahi[(size_t)(m0 + row) * EMBD + k0n + c8];
                ual[i] = *(const uint4*)&Alo[(size_t)(m0 + row) * EMBD + k0n + c8];
                ub[i]  = *(const uint4*)&Bhi[(size_t)(n0 + row) * EMBD + k0n + c8];
                ubl[i] = *(const uint4*)&Blo[(size_t)(n0 + row) * EMBD + k0n + c8];
            }
        }
        const uint32_t sbase = sb0 + (c & 1) * STAGE_NT;
        #pragma unroll
        for (int ks = 0; ks < 2; ks++) {
            const int k0 = ks * 16;
            uint32_t ah[4][4], al[4][4];
            #pragma unroll
            for (int mt = 0; mt < 4; mt++) {
                int r = wm * 64 + mt * 16 + arow;
                uint32_t ad = sbase + A_HI_O + (r * STR_K + k0 + acol8) * 2;
                ldsm4(ad, ah[mt][0], ah[mt][1], ah[mt][2], ah[mt][3]);
                ldsm4(ad + (A_LO_O - A_HI_O), al[mt][0], al[mt][1], al[mt][2], al[mt][3]);
            }
            uint32_t bh[4][2], bl[4][2];
            #pragma unroll
            for (int bt = 0; bt < 2; bt++) {
                int r = wn * 32 + bt * 16 + brow;
                uint32_t bd = sbase + B_HI_O + (r * STR_K + k0 + bcol8) * 2;
                ldsm4(bd, bh[2 * bt][0], bh[2 * bt][1], bh[2 * bt + 1][0], bh[2 * bt + 1][1]);
                ldsm4(bd + (B_LO_O - B_HI_O),
                      bl[2 * bt][0], bl[2 * bt][1], bl[2 * bt + 1][0], bl[2 * bt + 1][1]);
            }
            #pragma unroll
            for (int mt = 0; mt < 4; mt++)
                #pragma unroll
                for (int nt = 0; nt < 4; nt++) {
                    mma_bf16(acc[mt][nt], ah[mt], bh[nt][0], bh[nt][1]);
                    mma_bf16(acc[mt][nt], ah[mt], bl[nt][0], bl[nt][1]);
                    mma_bf16(acc[mt][nt], al[mt], bh[nt][0], bh[nt][1]);
                }
        }
        if (c + 1 < NC) {
            char* dst = sm + ((c + 1) & 1) * STAGE_NT;
            #pragma unroll
            for (int i = 0; i < 2; i++) {
                int seg = tid + i * 256, row = seg >> 2, c8 = (seg & 3) << 3;
                uint32_t off = (uint32_t)(row * STR_K + c8) * 2;
                *(uint4*)(dst + A_HI_O + off) = ua[i];
                *(uint4*)(dst + A_LO_O + off) = ual[i];
                *(uint4*)(dst + B_HI_O + off) = ub[i];
                *(uint4*)(dst + B_LO_O + off) = ubl[i];
            }
        }
        __syncthreads();
    }

    const int rofs = lane >> 2, cofs = (lane & 3) * 2;
    #pragma unroll
    for (int mt = 0; mt < 4; mt++)
        #pragma unroll
        for (int nt = 0; nt < 4; nt++) {
            int m = m0 + wm * 64 + mt * 16 + rofs;
            int n = n0 + wn * 32 + nt * 8 + cofs;
            if (WMODE == 0) {
                *(float2*)&Cf[(size_t)m * EMBD + n] =
                    make_float2(acc[mt][nt][0], acc[mt][nt][1]);
                *(float2*)&Cf[(size_t)(m + 8) * EMBD + n] =
                    make_float2(acc[mt][nt][2], acc[mt][nt][3]);
            } else {
                uint32_t h0, l0, h1, l1;
                pack2(acc[mt][nt][0], acc[mt][nt][1], h0, l0);
                pack2(acc[mt][nt][2], acc[mt][nt][3], h1, l1);
                *(uint32_t*)&Chi[(size_t)m * EMBD + n] = h0;
                *(uint32_t*)&Clo[(size_t)m * EMBD + n] = l0;
                *(uint32_t*)&Chi[(size_t)(m + 8) * EMBD + n] = h1;
                *(uint32_t*)&Clo[(size_t)(m + 8) * EMBD + n] = l1;
            }
        }
}

__global__ void __launch_bounds__(256)
mma_qkv()
{
    extern __shared__ __align__(16) char sm[];
    const int z = blockIdx.z;
    const size_t ra = (z == 0) ? R_X : R_C;
    const size_t rb = (z == 0) ? R_WQ : ((z == 1) ? R_WK : R_WV);
    const size_t rc = (z == 0) ? R_Q : ((z == 1) ? R_K : R_V);
    const __nv_bfloat16* Ahi = (const __nv_bfloat16*)(g_scr + ra);
    const __nv_bfloat16* Bhi = (const __nv_bfloat16*)(g_scr + rb);
    __nv_bfloat16* Chi = (__nv_bfloat16*)(g_scr + rc);
    nt_body_bf<1>(Ahi, Ahi + LO_ELEMS, Bhi, Bhi + LO_ELEMS,
                  nullptr, Chi, Chi + LO_ELEMS, sm);
}

__global__ void __launch_bounds__(256)
mma_out(float* __restrict__ out)
{
    extern __shared__ __align__(16) char sm[];
    const __nv_bfloat16* Ahi = (const __nv_bfloat16*)(g_scr + R_O);
    const __nv_bfloat16* Bhi = (const __nv_bfloat16*)(g_scr + R_WO);
    nt_body_bf<0>(Ahi, Ahi + LO_ELEMS, Bhi, Bhi + LO_ELEMS,
                  out, nullptr, nullptr, sm);
}

// ===========================================================================
// Fused attention on bf16 hi/lo Q/K/V with u8 mask.
// ===========================================================================
#define QSTR  72
#define F_LO  18432
#define FQ    0
#define FK0   36864
#define FK1   73728
#define FV0   110592
#define FV1   147456
#define FSMEM 184320

__device__ __forceinline__ void fill_bf(const __nv_bfloat16* __restrict__ hi,
                                        const __nv_bfloat16* __restrict__ lo,
                                        char* dst, int tid) {
    #pragma unroll
    for (int i = 0; i < 4; i++) {
        int seg = tid + i * 256, row = seg >> 3, c8 = (seg & 7) << 3;
        uint32_t off = (uint32_t)(row * QSTR + c8) * 2;
        *(uint4*)(dst + off)        = *(const uint4*)&hi[(size_t)row * EMBD + c8];
        *(uint4*)(dst + F_LO + off) = *(const uint4*)&lo[(size_t)row * EMBD + c8];
    }
}

#define SCORE_TILE(accv, smK)                                                    \
    do {                                                                          \
        _Pragma("unroll")                                                         \
        for (int ks = 0; ks < 4; ks++) {                                          \
            uint32_t bh[16][2], bl[16][2];                                        \
            _Pragma("unroll")                                                     \
            for (int bp = 0; bp < 8; bp++) {                                      \
                uint32_t bd = (smK) + ((bp * 16 + brow) * QSTR + ks * 16 + bcol8) * 2; \
                ldsm4(bd, bh[2 * bp][0], bh[2 * bp][1], bh[2 * bp + 1][0], bh[2 * bp + 1][1]); \
                ldsm4(bd + F_LO, bl[2 * bp][0], bl[2 * bp][1], bl[2 * bp + 1][0], bl[2 * bp + 1][1]); \
            }                                                                     \
            _Pragma("unroll")                                                     \
            for (int nt = 0; nt < 16; nt++) {                                     \
                mma_bf16(accv[nt], qh[ks], bh[nt][0], bh[nt][1]);                 \
                mma_bf16(accv[nt], qh[ks], bl[nt][0], bl[nt][1]);                 \
                mma_bf16(accv[nt], ql[ks], bh[nt][0], bh[nt][1]);                 \
            }                                                                     \
        }                                                                         \
    } while (0)

__global__ void __launch_bounds__(256)
fused_attn(float* __restrict__ Wt, int write_w)
{
    extern __shared__ __align__(16) char sm[];
    const uint32_t sb = smem_u32(sm);
    const int tid = threadIdx.x, lane = tid & 31, w = tid >> 5;
    const int z = blockIdx.y, b = z >> 4, h = z & 15;
    const int m0 = blockIdx.x * 128;

    const __nv_bfloat16* Qhi = (const __nv_bfloat16*)(g_scr + R_Q);
    const __nv_bfloat16* Khi = (const __nv_bfloat16*)(g_scr + R_K);
    const __nv_bfloat16* Vhi = (const __nv_bfloat16*)(g_scr + R_V);
    const size_t hb = (size_t)b * Tt * EMBD + h * HEAD;
    const __nv_bfloat16* Qb = Qhi + hb + (size_t)m0 * EMBD;
    const __nv_bfloat16* Kb = Khi + hb;
    const __nv_bfloat16* Vb = Vhi + hb;
    const uint8_t* mb = g_scr + R_M + (size_t)b * Tt * Tt + (size_t)m0 * Tt;

    const int g = lane >> 2, i2 = (lane & 3) << 1;
    const int arow = lane & 15, acol8 = (lane >> 4) << 3;
    const int brow = (lane & 7) + ((lane >> 4) << 3), bcol8 = ((lane >> 3) & 1) << 3;
    const int tbrow = (lane & 7) + (((lane >> 3) & 1) << 3), tbcol8 = (lane >> 4) << 3;

    fill_bf(Qb, Qb + LO_ELEMS, sm + FQ, tid);
    fill_bf(Kb, Kb + LO_ELEMS, sm + FK0, tid);
    __syncthreads();

    uint32_t qh[4][4], ql[4][4];
    #pragma unroll
    for (int ks = 0; ks < 4; ks++) {
        uint32_t ad = sb + FQ + ((w * 16 + arow) * QSTR + ks * 16 + acol8) * 2;
        ldsm4(ad, qh[ks][0], qh[ks][1], qh[ks][2], qh[ks][3]);
        ldsm4(ad + F_LO, ql[ks][0], ql[ks][1], ql[ks][2], ql[ks][3]);
    }

    const int trow = w * 16 + g;

    // ---------------- phase 1: stats ----------------
    float rm0 = -3.0e38f, rm1 = -3.0e38f, rs0 = 0.f, rs1 = 0.f;
    for (int st = 0; st < 8; st++) {
        if (st < 7) {
            const __nv_bfloat16* src = Kb + (size_t)(st + 1) * 128 * EMBD;
            fill_bf(src, src + LO_ELEMS, sm + (((st + 1) & 1) ? FK1 : FK0), tid);
        }
        float acc[16][4] = {};
        const uint32_t smK = sb + ((st & 1) ? FK1 : FK0);
        SCORE_TILE(acc, smK);

        const uint8_t* mr0 = mb + (size_t)trow * Tt + st * 128;
        const uint8_t* mr1 = mr0 + 8 * Tt;
        #pragma unroll
        for (int nt = 0; nt < 16; nt++) {
            uchar2 k0 = *(const uchar2*)&mr0[nt * 8 + i2];
            uchar2 k1 = *(const uchar2*)&mr1[nt * 8 + i2];
            acc[nt][0] = k0.x ? NEG_BIG : acc[nt][0] * 0.125f;
            acc[nt][1] = k0.y ? NEG_BIG : acc[nt][1] * 0.125f;
            acc[nt][2] = k1.x ? NEG_BIG : acc[nt][2] * 0.125f;
            acc[nt][3] = k1.y ? NEG_BIG : acc[nt][3] * 0.125f;
        }
        float t0 = -3.0e38f, t1 = -3.0e38f;
        #pragma unroll
        for (int nt = 0; nt < 16; nt++) {
            t0 = fmaxf(t0, fmaxf(acc[nt][0], acc[nt][1]));
            t1 = fmaxf(t1, fmaxf(acc[nt][2], acc[nt][3]));
        }
        t0 = fmaxf(t0, __shfl_xor_sync(0xffffffffu, t0, 1));
        t0 = fmaxf(t0, __shfl_xor_sync(0xffffffffu, t0, 2));
        t1 = fmaxf(t1, __shfl_xor_sync(0xffffffffu, t1, 1));
        t1 = fmaxf(t1, __shfl_xor_sync(0xffffffffu, t1, 2));
        float nm0 = fmaxf(rm0, t0), nm1 = fmaxf(rm1, t1);
        float s0 = 0.f, s1 = 0.f;
        #pragma unroll
        for (int nt = 0; nt < 16; nt++) {
            s0 += __expf(acc[nt][0] - nm0) + __expf(acc[nt][1] - nm0);
            s1 += __expf(acc[nt][2] - nm1) + __expf(acc[nt][3] - nm1);
        }
        s0 += __shfl_xor_sync(0xffffffffu, s0, 1);
        s0 += __shfl_xor_sync(0xffffffffu, s0, 2);
        s1 += __shfl_xor_sync(0xffffffffu, s1, 1);
        s1 += __shfl_xor_sync(0xffffffffu, s1, 2);
        rs0 = rs0 * __expf(rm0 - nm0) + s0;  rm0 = nm0;
        rs1 = rs1 * __expf(rm1 - nm1) + s1;  rm1 = nm1;
        __syncthreads();
    }
    const float inv0 = (rm0 <= -1e29f) ? 0.f : 1.f / rs0;
    const float inv1 = (rm1 <= -1e29f) ? 0.f : 1.f / rs1;

    // ---------------- phase 2: weights + AV ----------------
    fill_bf(Kb, Kb + LO_ELEMS, sm + FK0, tid);
    fill_bf(Vb, Vb + LO_ELEMS, sm + FV0, tid);
    __syncthreads();

    float acco[8][4] = {};
    float* wrow0 = Wt + (size_t)z * Tt * Tt + (size_t)(m0 + trow) * Tt;
    float* wrow1 = wrow0 + 8 * Tt;

    for (int st = 0; st < 8; st++) {
        if (st < 7) {
            const int nb = (st + 1) & 1;
            const __nv_bfloat16* ksrc = Kb + (size_t)(st + 1) * 128 * EMBD;
            const __nv_bfloat16* vsrc = Vb + (size_t)(st + 1) * 128 * EMBD;
            fill_bf(ksrc, ksrc + LO_ELEMS, sm + (nb ? FK1 : FK0), tid);
            fill_bf(vsrc, vsrc + LO_ELEMS, sm + (nb ? FV1 : FV0), tid);
        }
        float acc[16][4] = {};
        const uint32_t smK = sb + ((st & 1) ? FK1 : FK0);
        const uint32_t smV = sb + ((st & 1) ? FV1 : FV0);
        SCORE_TILE(acc, smK);

        const uint8_t* mr0 = mb + (size_t)trow * Tt + st * 128;
        const uint8_t* mr1 = mr0 + 8 * Tt;
        #pragma unroll
        for (int nt = 0; nt < 16; nt++) {
            uchar2 k0 = *(const uchar2*)&mr0[nt * 8 + i2];
            uchar2 k1 = *(const uchar2*)&mr1[nt * 8 + i2];
            float v0 = k0.x ? NEG_BIG : acc[nt][0] * 0.125f;
            float v1 = k0.y ? NEG_BIG : acc[nt][1] * 0.125f;
            float v2 = k1.x ? NEG_BIG : acc[nt][2] * 0.125f;
            float v3 = k1.y ? NEG_BIG : acc[nt][3] * 0.125f;
            acc[nt][0] = __expf(v0 - rm0) * inv0;
            acc[nt][1] = __expf(v1 - rm0) * inv0;
            acc[nt][2] = __expf(v2 - rm1) * inv1;
            acc[nt][3] = __expf(v3 - rm1) * inv1;
        }
        if (write_w) {
            #pragma unroll
            for (int nt = 0; nt < 16; nt++) {
                *(float2*)&wrow0[st * 128 + nt * 8 + i2] = make_float2(acc[nt][0], acc[nt][1]);
                *(float2*)&wrow1[st * 128 + nt * 8 + i2] = make_float2(acc[nt][2], acc[nt][3]);
            }
        }
        #pragma unroll
        for (int j = 0; j < 8; j++) {
            uint32_t ph[4], pl[4];
            pack2(acc[2 * j][0],     acc[2 * j][1],     ph[0], pl[0]);
            pack2(acc[2 * j][2],     acc[2 * j][3],     ph[1], pl[1]);
            pack2(acc[2 * j + 1][0], acc[2 * j + 1][1], ph[2], pl[2]);
            pack2(acc[2 * j + 1][2], acc[2 * j + 1][3], ph[3], pl[3]);
            uint32_t vh[8][2], vl[8][2];
            #pragma unroll
            for (int bt = 0; bt < 4; bt++) {
                uint32_t vd = smV + ((j * 16 + tbrow) * QSTR + bt * 16 + tbcol8) * 2;
                ldsm4t(vd, vh[2 * bt][0], vh[2 * bt][1], vh[2 * bt + 1][0], vh[2 * bt + 1][1]);
                ldsm4t(vd + F_LO, vl[2 * bt][0], vl[2 * bt][1], vl[2 * bt + 1][0], vl[2 * bt + 1][1]);
            }
            #pragma unroll
            for (int ntv = 0; ntv < 8; ntv++) {
                mma_bf16(acco[ntv], ph, vh[ntv][0], vh[ntv][1]);
                mma_bf16(acco[ntv], ph, vl[ntv][0], vl[ntv][1]);
                mma_bf16(acco[ntv], pl, vh[ntv][0], vh[ntv][1]);
            }
        }
        __syncthreads();
    }

    // write O as bf16 hi/lo (consumed by mma_out)
    __nv_bfloat16* Ohi = (__nv_bfloat16*)(g_scr + R_O);
    __nv_bfloat16* Ob = Ohi + (size_t)(b * Tt + m0 + trow) * EMBD + h * HEAD;
    __nv_bfloat16* ObL = Ob + LO_ELEMS;
    #pragma unroll
    for (int ntv = 0; ntv < 8; ntv++) {
        uint32_t h0, l0, h1, l1;
        pack2(acco[ntv][0], acco[ntv][1], h0, l0);
        pack2(acco[ntv][2], acco[ntv][3], h1, l1);
        *(uint32_t*)&Ob[ntv * 8 + i2] = h0;
        *(uint32_t*)&ObL[ntv * 8 + i2] = l0;
        *(uint32_t*)&Ob[8 * EMBD + ntv * 8 + i2] = h1;
        *(uint32_t*)&ObL[8 * EMBD + ntv * 8 + i2] = l1;
    }
}

// ===========================================================================
extern "C" void kernel_launch(void* const* d_in, const int* in_sizes, int n_in,
                              void* d_out, int out_size)
{
    const float* x    = (const float*)d_in[0];
    const float* ctx  = (const float*)d_in[1];
    const int*   mask = (const int*)d_in[2];
    const float* WQ = (const float*)d_in[3];
    const float* WK = (const float*)d_in[4];
    const float* WV = (const float*)d_in[5];
    const float* WO = (const float*)d_in[6];
    float* out = (float*)d_out;

    const size_t merged_elems = (size_t)BTR * EMBD;
    const size_t weight_elems = (size_t)Bb * Hh * Tt * Tt;
    const int write_w = ((size_t)out_size >= merged_elems + weight_elems) ? 1 : 0;
    float* wt = write_w ? (out + merged_elems) : out;

    const int SMEM_NT = 2 * STAGE_NT;   // 80 KB
    cudaFuncSetAttribute(mma_qkv, cudaFuncAttributeMaxDynamicSharedMemorySize, SMEM_NT);
    cudaFuncSetAttribute(mma_out, cudaFuncAttributeMaxDynamicSharedMemorySize, SMEM_NT);
    cudaFuncSetAttribute(fused_attn, cudaFuncAttributeMaxDynamicSharedMemorySize, FSMEM);

    dim3 blk(256);

    // prep: fp32 -> bf16 hi/lo, mask -> u8
    dim3 gp(4096, 1, 6);
    prep_all<<<gp, blk>>>(x, ctx, WQ, WK, WV, WO);
    prep_mask<<<4096, blk>>>(mask);

    // Q/K/V projections (bf16 in, bf16 hi/lo out)
    dim3 gqkv(EMBD / 128, BTR / 128, 3);
    mma_qkv<<<gqkv, blk, SMEM_NT>>>();

    // fused scores+softmax+weights+AV
    dim3 gf(Tt / 128, Bb * Hh);
    fused_attn<<<gf, blk, FSMEM>>>(wt, write_w);

    // output projection (bf16 in, fp32 out)
    dim3 gout(EMBD / 128, BTR / 128);
    mma_out<<<gout, blk, SMEM_NT>>>(out);
}

// round 7
// speedup vs baseline: 1.0368x; 1.0368x over previous
#include <cuda_runtime.h>
#include <cuda_bf16.h>
#include <cstdint>

#define Bb   4
#define Tt   1024
#define EMBD 1024
#define Hh   16
#define HEAD 64
#define BTR  (Bb * Tt)
#define NEG_BIG (-1e30f)

// fp32 scratch
static __device__ float g_Q[(size_t)BTR * EMBD];
static __device__ float g_K[(size_t)BTR * EMBD];
static __device__ float g_V[(size_t)BTR * EMBD];
static __device__ float g_O[(size_t)BTR * EMBD];
static __device__ float g_W[(size_t)Bb * Hh * Tt * Tt];

// bf16 hi/lo prepped operands + u8 mask
#define MB1 (1024ull * 1024ull)
#define R_X   (0ull  * MB1)
#define R_C   (16ull * MB1)
#define R_WQ  (32ull * MB1)
#define R_WK  (48ull * MB1)
#define R_WV  (64ull * MB1)
#define R_WO  (80ull * MB1)
#define R_M   (96ull * MB1)
#define SCR_SZ (100ull * MB1)
#define LO_ELEMS (4ull * MB1)     // bf16 elems between hi and lo halves
static __device__ __align__(16) uint8_t g_scr[SCR_SZ];

// ===========================================================================
// helpers
// ===========================================================================
__device__ __forceinline__ uint32_t smem_u32(const void* p) {
    uint32_t a;
    asm("{ .reg .u64 t; cvta.to.shared.u64 t, %1; cvt.u32.u64 %0, t; }" : "=r"(a) : "l"(p));
    return a;
}
__device__ __forceinline__ void ldsm4(uint32_t addr, uint32_t& r0, uint32_t& r1,
                                      uint32_t& r2, uint32_t& r3) {
    asm volatile("ldmatrix.sync.aligned.m8n8.x4.shared.b16 {%0,%1,%2,%3}, [%4];"
                 : "=r"(r0), "=r"(r1), "=r"(r2), "=r"(r3) : "r"(addr));
}
__device__ __forceinline__ void ldsm4t(uint32_t addr, uint32_t& r0, uint32_t& r1,
                                       uint32_t& r2, uint32_t& r3) {
    asm volatile("ldmatrix.sync.aligned.m8n8.x4.trans.shared.b16 {%0,%1,%2,%3}, [%4];"
                 : "=r"(r0), "=r"(r1), "=r"(r2), "=r"(r3) : "r"(addr));
}
__device__ __forceinline__ void mma_bf16(float (&d)[4], const uint32_t (&a)[4],
                                         uint32_t b0, uint32_t b1) {
    asm volatile("mma.sync.aligned.m16n8k16.row.col.f32.bf16.bf16.f32 "
                 "{%0,%1,%2,%3},{%4,%5,%6,%7},{%8,%9},{%0,%1,%2,%3};"
                 : "+f"(d[0]), "+f"(d[1]), "+f"(d[2]), "+f"(d[3])
                 : "r"(a[0]), "r"(a[1]), "r"(a[2]), "r"(a[3]), "r"(b0), "r"(b1));
}
__device__ __forceinline__ void cvt_hilo(float4 v, uint2& hi, uint2& lo) {
    __nv_bfloat162 h0 = __floats2bfloat162_rn(v.x, v.y);
    __nv_bfloat162 h1 = __floats2bfloat162_rn(v.z, v.w);
    float rx = v.x - __bfloat162float(h0.x);
    float ry = v.y - __bfloat162float(h0.y);
    float rz = v.z - __bfloat162float(h1.x);
    float rw = v.w - __bfloat162float(h1.y);
    __nv_bfloat162 l0 = __floats2bfloat162_rn(rx, ry);
    __nv_bfloat162 l1 = __floats2bfloat162_rn(rz, rw);
    hi = make_uint2(*(uint32_t*)&h0, *(uint32_t*)&h1);
    lo = make_uint2(*(uint32_t*)&l0, *(uint32_t*)&l1);
}
__device__ __forceinline__ void pack2(float x, float y, uint32_t& h, uint32_t& l) {
    __nv_bfloat162 hh = __floats2bfloat162_rn(x, y);
    float rx = x - __bfloat162float(hh.x);
    float ry = y - __bfloat162float(hh.y);
    __nv_bfloat162 ll = __floats2bfloat162_rn(rx, ry);
    h = *(uint32_t*)&hh;
    l = *(uint32_t*)&ll;
}

// ===========================================================================
// prep: fp32 -> bf16 hi/lo (6 matrices); mask int32 -> u8
// ===========================================================================
__global__ void __launch_bounds__(256)
prep_all(const float* __restrict__ x, const float* __restrict__ ctx,
         const float* __restrict__ wq, const float* __restrict__ wk,
         const float* __restrict__ wv, const float* __restrict__ wo)
{
    const int z = blockIdx.z;
    const float* srcs[6] = {x, ctx, wq, wk, wv, wo};
    const size_t offs[6] = {R_X, R_C, R_WQ, R_WK, R_WV, R_WO};
    const float4* s = (const float4*)srcs[z];
    uint2* h = (uint2*)(g_scr + offs[z]);
    uint2* l = (uint2*)(g_scr + offs[z] + 8ull * MB1);
    size_t i = (size_t)blockIdx.x * 256 + threadIdx.x;
    uint2 hh, ll;
    cvt_hilo(s[i], hh, ll);
    h[i] = hh;
    l[i] = ll;
}

__global__ void __launch_bounds__(256)
prep_mask(const int* __restrict__ m)
{
    size_t i = (size_t)blockIdx.x * 256 + threadIdx.x;
    int4 v = ((const int4*)m)[i];
    uchar4 o;
    o.x = v.x ? 1 : 0; o.y = v.y ? 1 : 0; o.z = v.z ? 1 : 0; o.w = v.w ? 1 : 0;
    ((uchar4*)(g_scr + R_M))[i] = o;
}

// ===========================================================================
// NT GEMM: C(fp32) = A * B^T. B always prepped bf16 hi/lo.
// ABF=true: A prepped bf16 hi/lo; ABF=false: A fp32 (converted in-loop).
// 128x128 block, BK=32, 8 warps (2Mx4N), bf16x3.
// ===========================================================================
#define STR_K  40
#define A_HI_O 0
#define A_LO_O 10240
#define B_HI_O 20480
#define B_LO_O 30720
#define STAGE_NT 40960

template <bool ABF>
__device__ __forceinline__ void nt_body2(
    const float* __restrict__ Af,
    const __nv_bfloat16* __restrict__ Ahi, const __nv_bfloat16* __restrict__ Alo,
    const __nv_bfloat16* __restrict__ Bhi, const __nv_bfloat16* __restrict__ Blo,
    float* __restrict__ Cf, char* sm)
{
    const int tid = threadIdx.x, lane = tid & 31, wid = tid >> 5;
    const int m0 = blockIdx.y * 128;
    const int n0 = blockIdx.x * 128;
    const int NC = EMBD / 32;

    float acc[4][4][4] = {};
    float4 laf[4];
    uint4 ua[2], ual[2], ub[2], ubl[2];

    // prologue: stage 0 loads
    if (ABF) {
        #pragma unroll
        for (int i = 0; i < 2; i++) {
            int seg = tid + i * 256, row = seg >> 2, c8 = (seg & 3) << 3;
            ua[i]  = *(const uint4*)&Ahi[(size_t)(m0 + row) * EMBD + c8];
            ual[i] = *(const uint4*)&Alo[(size_t)(m0 + row) * EMBD + c8];
        }
    } else {
        #pragma unroll
        for (int i = 0; i < 4; i++) {
            int seg = tid + i * 256, row = seg >> 3, c4 = (seg & 7) << 2;
            laf[i] = *(const float4*)&Af[(size_t)(m0 + row) * EMBD + c4];
        }
    }
    #pragma unroll
    for (int i = 0; i < 2; i++) {
        int seg = tid + i * 256, row = seg >> 2, c8 = (seg & 3) << 3;
        ub[i]  = *(const uint4*)&Bhi[(size_t)(n0 + row) * EMBD + c8];
        ubl[i] = *(const uint4*)&Blo[(size_t)(n0 + row) * EMBD + c8];
    }
    // prologue stores
    if (ABF) {
        #pragma unroll
        for (int i = 0; i < 2; i++) {
            int seg = tid + i * 256, row = seg >> 2, c8 = (seg & 3) << 3;
            uint32_t off = (uint32_t)(row * STR_K + c8) * 2;
            *(uint4*)(sm + A_HI_O + off) = ua[i];
            *(uint4*)(sm + A_LO_O + off) = ual[i];
        }
    } else {
        #pragma unroll
        for (int i = 0; i < 4; i++) {
            int seg = tid + i * 256, row = seg >> 3, c4 = (seg & 7) << 2;
            uint2 h, l;
            cvt_hilo(laf[i], h, l);
            uint32_t off = (uint32_t)(row * STR_K + c4) * 2;
            *(uint2*)(sm + A_HI_O + off) = h;
            *(uint2*)(sm + A_LO_O + off) = l;
        }
    }
    #pragma unroll
    for (int i = 0; i < 2; i++) {
        int seg = tid + i * 256, row = seg >> 2, c8 = (seg & 3) << 3;
        uint32_t off = (uint32_t)(row * STR_K + c8) * 2;
        *(uint4*)(sm + B_HI_O + off) = ub[i];
        *(uint4*)(sm + B_LO_O + off) = ubl[i];
    }
    __syncthreads();

    const int wm = wid >> 2, wn = wid & 3;
    const int arow = lane & 15, acol8 = (lane >> 4) << 3;
    const int brow = (lane & 7) + ((lane >> 4) << 3), bcol8 = ((lane >> 3) & 1) << 3;
    const uint32_t sb0 = smem_u32(sm);

    for (int c = 0; c < NC; c++) {
        if (c + 1 < NC) {
            int k0n = (c + 1) * 32;
            if (ABF) {
                #pragma unroll
                for (int i = 0; i < 2; i++) {
                    int seg = tid + i * 256, row = seg >> 2, c8 = (seg & 3) << 3;
                    ua[i]  = *(const uint4*)&Ahi[(size_t)(m0 + row) * EMBD + k0n + c8];
                    ual[i] = *(const uint4*)&Alo[(size_t)(m0 + row) * EMBD + k0n + c8];
                }
            } else {
                #pragma unroll
                for (int i = 0; i < 4; i++) {
                    int seg = tid + i * 256, row = seg >> 3, c4 = (seg & 7) << 2;
                    laf[i] = *(const float4*)&Af[(size_t)(m0 + row) * EMBD + k0n + c4];
                }
            }
            #pragma unroll
            for (int i = 0; i < 2; i++) {
                int seg = tid + i * 256, row = seg >> 2, c8 = (seg & 3) << 3;
                ub[i]  = *(const uint4*)&Bhi[(size_t)(n0 + row) * EMBD + k0n + c8];
                ubl[i] = *(const uint4*)&Blo[(size_t)(n0 + row) * EMBD + k0n + c8];
            }
        }
        const uint32_t sbase = sb0 + (c & 1) * STAGE_NT;
        #pragma unroll
        for (int ks = 0; ks < 2; ks++) {
            const int k0 = ks * 16;
            uint32_t ah[4][4], al[4][4];
            #pragma unroll
            for (int mt = 0; mt < 4; mt++) {
                int r = wm * 64 + mt * 16 + arow;
                uint32_t ad = sbase + A_HI_O + (r * STR_K + k0 + acol8) * 2;
                ldsm4(ad, ah[mt][0], ah[mt][1], ah[mt][2], ah[mt][3]);
                ldsm4(ad + (A_LO_O - A_HI_O), al[mt][0], al[mt][1], al[mt][2], al[mt][3]);
            }
            uint32_t bh[4][2], bl[4][2];
            #pragma unroll
            for (int bt = 0; bt < 2; bt++) {
                int r = wn * 32 + bt * 16 + brow;
                uint32_t bd = sbase + B_HI_O + (r * STR_K + k0 + bcol8) * 2;
                ldsm4(bd, bh[2 * bt][0], bh[2 * bt][1], bh[2 * bt + 1][0], bh[2 * bt + 1][1]);
                ldsm4(bd + (B_LO_O - B_HI_O),
                      bl[2 * bt][0], bl[2 * bt][1], bl[2 * bt + 1][0], bl[2 * bt + 1][1]);
            }
            #pragma unroll
            for (int mt = 0; mt < 4; mt++)
                #pragma unroll
                for (int nt = 0; nt < 4; nt++) {
                    mma_bf16(acc[mt][nt], ah[mt], bh[nt][0], bh[nt][1]);
                    mma_bf16(acc[mt][nt], ah[mt], bl[nt][0], bl[nt][1]);
                    mma_bf16(acc[mt][nt], al[mt], bh[nt][0], bh[nt][1]);
                }
        }
        if (c + 1 < NC) {
            char* dst = sm + ((c + 1) & 1) * STAGE_NT;
            if (ABF) {
                #pragma unroll
                for (int i = 0; i < 2; i++) {
                    int seg = tid + i * 256, row = seg >> 2, c8 = (seg & 3) << 3;
                    uint32_t off = (uint32_t)(row * STR_K + c8) * 2;
                    *(uint4*)(dst + A_HI_O + off) = ua[i];
                    *(uint4*)(dst + A_LO_O + off) = ual[i];
                }
            } else {
                #pragma unroll
                for (int i = 0; i < 4; i++) {
                    int seg = tid + i * 256, row = seg >> 3, c4 = (seg & 7) << 2;
                    uint2 h, l;
                    cvt_hilo(laf[i], h, l);
                    uint32_t off = (uint32_t)(row * STR_K + c4) * 2;
                    *(uint2*)(dst + A_HI_O + off) = h;
                    *(uint2*)(dst + A_LO_O + off) = l;
                }
            }
            #pragma unroll
            for (int i = 0; i < 2; i++) {
                int seg = tid + i * 256, row = seg >> 2, c8 = (seg & 3) << 3;
                uint32_t off = (uint32_t)(row * STR_K + c8) * 2;
                *(uint4*)(dst + B_HI_O + off) = ub[i];
                *(uint4*)(dst + B_LO_O + off) = ubl[i];
            }
        }
        __syncthreads();
    }

    const int rofs = lane >> 2, cofs = (lane & 3) * 2;
    #pragma unroll
    for (int mt = 0; mt < 4; mt++)
        #pragma unroll
        for (int nt = 0; nt < 4; nt++) {
            int m = m0 + wm * 64 + mt * 16 + rofs;
            int n = n0 + wn * 32 + nt * 8 + cofs;
            *(float2*)&Cf[(size_t)m * EMBD + n] =
                make_float2(acc[mt][nt][0], acc[mt][nt][1]);
            *(float2*)&Cf[(size_t)(m + 8) * EMBD + n] =
                make_float2(acc[mt][nt][2], acc[mt][nt][3]);
        }
}

__global__ void __launch_bounds__(256)
mma_qkv(float* __restrict__ qp, float* __restrict__ kp, float* __restrict__ vp)
{
    extern __shared__ __align__(16) char sm[];
    const int z = blockIdx.z;
    const size_t ra = (z == 0) ? R_X : R_C;
    const size_t rb = (z == 0) ? R_WQ : ((z == 1) ? R_WK : R_WV);
    float* Cb = (z == 0) ? qp : ((z == 1) ? kp : vp);
    const __nv_bfloat16* Ahi = (const __nv_bfloat16*)(g_scr + ra);
    const __nv_bfloat16* Bhi = (const __nv_bfloat16*)(g_scr + rb);
    nt_body2<true>(nullptr, Ahi, Ahi + LO_ELEMS, Bhi, Bhi + LO_ELEMS, Cb, sm);
}

__global__ void __launch_bounds__(256)
mma_out(const float* __restrict__ A, float* __restrict__ out)
{
    extern __shared__ __align__(16) char sm[];
    const __nv_bfloat16* Bhi = (const __nv_bfloat16*)(g_scr + R_WO);
    nt_body2<false>(A, nullptr, nullptr, Bhi, Bhi + LO_ELEMS, out, sm);
}

// ===========================================================================
// Fused attention — EXACT R5 structure (fp32 Q/K/V fills, fp32 O write);
// only the mask source is u8 now.
// ===========================================================================
#define QSTR  72
#define F_LO  18432
#define FQ    0
#define FK0   36864
#define FK1   73728
#define FV0   110592
#define FV1   147456
#define FSMEM 184320

__device__ __forceinline__ void fill64(const float* __restrict__ src, char* dst, int tid) {
    #pragma unroll
    for (int i = 0; i < 8; i++) {
        int seg = tid + i * 256, row = seg >> 4, c4 = (seg & 15) << 2;
        float4 v = *(const float4*)&src[(size_t)row * EMBD + c4];
        uint2 h, l;
        cvt_hilo(v, h, l);
        uint32_t off = (uint32_t)(row * QSTR + c4) * 2;
        *(uint2*)(dst + off) = h;
        *(uint2*)(dst + F_LO + off) = l;
    }
}

#define SCORE_TILE(accv, smK)                                                    \
    do {                                                                          \
        _Pragma("unroll")                                                         \
        for (int ks = 0; ks < 4; ks++) {                                          \
            uint32_t bh[16][2], bl[16][2];                                        \
            _Pragma("unroll")                                                     \
            for (int bp = 0; bp < 8; bp++) {                                      \
                uint32_t bd = (smK) + ((bp * 16 + brow) * QSTR + ks * 16 + bcol8) * 2; \
                ldsm4(bd, bh[2 * bp][0], bh[2 * bp][1], bh[2 * bp + 1][0], bh[2 * bp + 1][1]); \
                ldsm4(bd + F_LO, bl[2 * bp][0], bl[2 * bp][1], bl[2 * bp + 1][0], bl[2 * bp + 1][1]); \
            }                                                                     \
            _Pragma("unroll")                                                     \
            for (int nt = 0; nt < 16; nt++) {                                     \
                mma_bf16(accv[nt], qh[ks], bh[nt][0], bh[nt][1]);                 \
                mma_bf16(accv[nt], qh[ks], bl[nt][0], bl[nt][1]);                 \
                mma_bf16(accv[nt], ql[ks], bh[nt][0], bh[nt][1]);                 \
            }                                                                     \
        }                                                                         \
    } while (0)

__global__ void __launch_bounds__(256)
fused_attn(const float* __restrict__ Q, const float* __restrict__ K,
           const float* __restrict__ V,
           float* __restrict__ Wt, float* __restrict__ O, int write_w)
{
    extern __shared__ __align__(16) char sm[];
    const uint32_t sb = smem_u32(sm);
    const int tid = threadIdx.x, lane = tid & 31, w = tid >> 5;
    const int z = blockIdx.y, b = z >> 4, h = z & 15;
    const int m0 = blockIdx.x * 128;

    const float* Qb = Q + (size_t)b * Tt * EMBD + h * HEAD;
    const float* Kb = K + (size_t)b * Tt * EMBD + h * HEAD;
    const float* Vb = V + (size_t)b * Tt * EMBD + h * HEAD;
    const uint8_t* mb = g_scr + R_M + (size_t)b * Tt * Tt + (size_t)m0 * Tt;

    const int g = lane >> 2, i2 = (lane & 3) << 1;
    const int arow = lane & 15, acol8 = (lane >> 4) << 3;
    const int brow = (lane & 7) + ((lane >> 4) << 3), bcol8 = ((lane >> 3) & 1) << 3;
    const int tbrow = (lane & 7) + (((lane >> 3) & 1) << 3), tbcol8 = (lane >> 4) << 3;

    fill64(Qb + (size_t)m0 * EMBD, sm + FQ, tid);
    fill64(Kb, sm + FK0, tid);
    __syncthreads();

    uint32_t qh[4][4], ql[4][4];
    #pragma unroll
    for (int ks = 0; ks < 4; ks++) {
        uint32_t ad = sb + FQ + ((w * 16 + arow) * QSTR + ks * 16 + acol8) * 2;
        ldsm4(ad, qh[ks][0], qh[ks][1], qh[ks][2], qh[ks][3]);
        ldsm4(ad + F_LO, ql[ks][0], ql[ks][1], ql[ks][2], ql[ks][3]);
    }

    const int trow = w * 16 + g;

    // ---------------- phase 1: stats ----------------
    float rm0 = -3.0e38f, rm1 = -3.0e38f, rs0 = 0.f, rs1 = 0.f;
    for (int st = 0; st < 8; st++) {
        if (st < 7) fill64(Kb + (size_t)(st + 1) * 128 * EMBD,
                           sm + (((st + 1) & 1) ? FK1 : FK0), tid);
        float acc[16][4] = {};
        const uint32_t smK = sb + ((st & 1) ? FK1 : FK0);
        SCORE_TILE(acc, smK);

        const uint8_t* mr0 = mb + (size_t)trow * Tt + st * 128;
        const uint8_t* mr1 = mr0 + 8 * Tt;
        #pragma unroll
        for (int nt = 0; nt < 16; nt++) {
            uchar2 k0 = *(const uchar2*)&mr0[nt * 8 + i2];
            uchar2 k1 = *(const uchar2*)&mr1[nt * 8 + i2];
            acc[nt][0] = k0.x ? NEG_BIG : acc[nt][0] * 0.125f;
            acc[nt][1] = k0.y ? NEG_BIG : acc[nt][1] * 0.125f;
            acc[nt][2] = k1.x ? NEG_BIG : acc[nt][2] * 0.125f;
            acc[nt][3] = k1.y ? NEG_BIG : acc[nt][3] * 0.125f;
        }
        float t0 = -3.0e38f, t1 = -3.0e38f;
        #pragma unroll
        for (int nt = 0; nt < 16; nt++) {
            t0 = fmaxf(t0, fmaxf(acc[nt][0], acc[nt][1]));
            t1 = fmaxf(t1, fmaxf(acc[nt][2], acc[nt][3]));
        }
        t0 = fmaxf(t0, __shfl_xor_sync(0xffffffffu, t0, 1));
        t0 = fmaxf(t0, __shfl_xor_sync(0xffffffffu, t0, 2));
        t1 = fmaxf(t1, __shfl_xor_sync(0xffffffffu, t1, 1));
        t1 = fmaxf(t1, __shfl_xor_sync(0xffffffffu, t1, 2));
        float nm0 = fmaxf(rm0, t0), nm1 = fmaxf(rm1, t1);
        float s0 = 0.f, s1 = 0.f;
        #pragma unroll
        for (int nt = 0; nt < 16; nt++) {
            s0 += __expf(acc[nt][0] - nm0) + __expf(acc[nt][1] - nm0);
            s1 += __expf(acc[nt][2] - nm1) + __expf(acc[nt][3] - nm1);
        }
        s0 += __shfl_xor_sync(0xffffffffu, s0, 1);
        s0 += __shfl_xor_sync(0xffffffffu, s0, 2);
        s1 += __shfl_xor_sync(0xffffffffu, s1, 1);
        s1 += __shfl_xor_sync(0xffffffffu, s1, 2);
        rs0 = rs0 * __expf(rm0 - nm0) + s0;  rm0 = nm0;
        rs1 = rs1 * __expf(rm1 - nm1) + s1;  rm1 = nm1;
        __syncthreads();
    }
    const float inv0 = (rm0 <= -1e29f) ? 0.f : 1.f / rs0;
    const float inv1 = (rm1 <= -1e29f) ? 0.f : 1.f / rs1;

    // ---------------- phase 2: weights + AV ----------------
    fill64(Kb, sm + FK0, tid);
    fill64(Vb, sm + FV0, tid);
    __syncthreads();

    float acco[8][4] = {};
    float* wrow0 = Wt + (size_t)z * Tt * Tt + (size_t)(m0 + trow) * Tt;
    float* wrow1 = wrow0 + 8 * Tt;

    for (int st = 0; st < 8; st++) {
        if (st < 7) {
            const int nb = (st + 1) & 1;
            fill64(Kb + (size_t)(st + 1) * 128 * EMBD, sm + (nb ? FK1 : FK0), tid);
            fill64(Vb + (size_t)(st + 1) * 128 * EMBD, sm + (nb ? FV1 : FV0), tid);
        }
        float acc[16][4] = {};
        const uint32_t smK = sb + ((st & 1) ? FK1 : FK0);
        const uint32_t smV = sb + ((st & 1) ? FV1 : FV0);
        SCORE_TILE(acc, smK);

        const uint8_t* mr0 = mb + (size_t)trow * Tt + st * 128;
        const uint8_t* mr1 = mr0 + 8 * Tt;
        #pragma unroll
        for (int nt = 0; nt < 16; nt++) {
            uchar2 k0 = *(const uchar2*)&mr0[nt * 8 + i2];
            uchar2 k1 = *(const uchar2*)&mr1[nt * 8 + i2];
            float v0 = k0.x ? NEG_BIG : acc[nt][0] * 0.125f;
            float v1 = k0.y ? NEG_BIG : acc[nt][1] * 0.125f;
            float v2 = k1.x ? NEG_BIG : acc[nt][2] * 0.125f;
            float v3 = k1.y ? NEG_BIG : acc[nt][3] * 0.125f;
            acc[nt][0] = __expf(v0 - rm0) * inv0;
            acc[nt][1] = __expf(v1 - rm0) * inv0;
            acc[nt][2] = __expf(v2 - rm1) * inv1;
            acc[nt][3] = __expf(v3 - rm1) * inv1;
        }
        if (write_w) {
            #pragma unroll
            for (int nt = 0; nt < 16; nt++) {
                *(float2*)&wrow0[st * 128 + nt * 8 + i2] = make_float2(acc[nt][0], acc[nt][1]);
                *(float2*)&wrow1[st * 128 + nt * 8 + i2] = make_float2(acc[nt][2], acc[nt][3]);
            }
        }
        #pragma unroll
        for (int j = 0; j < 8; j++) {
            uint32_t ph[4], pl[4];
            pack2(acc[2 * j][0],     acc[2 * j][1],     ph[0], pl[0]);
            pack2(acc[2 * j][2],     acc[2 * j][3],     ph[1], pl[1]);
            pack2(acc[2 * j + 1][0], acc[2 * j + 1][1], ph[2], pl[2]);
            pack2(acc[2 * j + 1][2], acc[2 * j + 1][3], ph[3], pl[3]);
            uint32_t vh[8][2], vl[8][2];
            #pragma unroll
            for (int bt = 0; bt < 4; bt++) {
                uint32_t vd = smV + ((j * 16 + tbrow) * QSTR + bt * 16 + tbcol8) * 2;
                ldsm4t(vd, vh[2 * bt][0], vh[2 * bt][1], vh[2 * bt + 1][0], vh[2 * bt + 1][1]);
                ldsm4t(vd + F_LO, vl[2 * bt][0], vl[2 * bt][1], vl[2 * bt + 1][0], vl[2 * bt + 1][1]);
            }
            #pragma unroll
            for (int ntv = 0; ntv < 8; ntv++) {
                mma_bf16(acco[ntv], ph, vh[ntv][0], vh[ntv][1]);
                mma_bf16(acco[ntv], ph, vl[ntv][0], vl[ntv][1]);
                mma_bf16(acco[ntv], pl, vh[ntv][0], vh[ntv][1]);
            }
        }
        __syncthreads();
    }

    float* Ob = O + (size_t)b * Tt * EMBD + h * HEAD + (size_t)(m0 + trow) * EMBD;
    #pragma unroll
    for (int ntv = 0; ntv < 8; ntv++) {
        *(float2*)&Ob[ntv * 8 + i2] = make_float2(acco[ntv][0], acco[ntv][1]);
        *(float2*)&Ob[8 * EMBD + ntv * 8 + i2] = make_float2(acco[ntv][2], acco[ntv][3]);
    }
}

// ===========================================================================
extern "C" void kernel_launch(void* const* d_in, const int* in_sizes, int n_in,
                              void* d_out, int out_size)
{
    const float* x    = (const float*)d_in[0];
    const float* ctx  = (const float*)d_in[1];
    const int*   mask = (const int*)d_in[2];
    const float* WQ = (const float*)d_in[3];
    const float* WK = (const float*)d_in[4];
    const float* WV = (const float*)d_in[5];
    const float* WO = (const float*)d_in[6];
    float* out = (float*)d_out;

    float *qp, *kp, *vp, *op;
    cudaGetSymbolAddress((void**)&qp, g_Q);
    cudaGetSymbolAddress((void**)&kp, g_K);
    cudaGetSymbolAddress((void**)&vp, g_V);
    cudaGetSymbolAddress((void**)&op, g_O);

    const size_t merged_elems = (size_t)BTR * EMBD;
    const size_t weight_elems = (size_t)Bb * Hh * Tt * Tt;
    const int write_w = ((size_t)out_size >= merged_elems + weight_elems) ? 1 : 0;
    float* wt;
    if (write_w) {
        wt = out + merged_elems;
    } else {
        cudaGetSymbolAddress((void**)&wt, g_W);
    }

    const int SMEM_NT = 2 * STAGE_NT;   // 80 KB
    cudaFuncSetAttribute(mma_qkv, cudaFuncAttributeMaxDynamicSharedMemorySize, SMEM_NT);
    cudaFuncSetAttribute(mma_out, cudaFuncAttributeMaxDynamicSharedMemorySize, SMEM_NT);
    cudaFuncSetAttribute(fused_attn, cudaFuncAttributeMaxDynamicSharedMemorySize, FSMEM);

    dim3 blk(256);

    // prep
    dim3 gp(4096, 1, 6);
    prep_all<<<gp, blk>>>(x, ctx, WQ, WK, WV, WO);
    prep_mask<<<4096, blk>>>(mask);

    // projections (bf16 operands in, fp32 out)
    dim3 gqkv(EMBD / 128, BTR / 128, 3);
    mma_qkv<<<gqkv, blk, SMEM_NT>>>(qp, kp, vp);

    // fused attention (R5 structure + u8 mask)
    dim3 gf(Tt / 128, Bb * Hh);
    fused_attn<<<gf, blk, FSMEM>>>(qp, kp, vp, wt, op, write_w);

    // output projection (A fp32, B bf16)
    dim3 gout(EMBD / 128, BTR / 128);
    mma_out<<<gout, blk, SMEM_NT>>>(op, out);
}

// round 8
// speedup vs baseline: 1.2849x; 1.2392x over previous
#include <cuda_runtime.h>
#include <cuda_bf16.h>
#include <cstdint>

#define Bb   4
#define Tt   1024
#define EMBD 1024
#define Hh   16
#define HEAD 64
#define BTR  (Bb * Tt)
#define NEG_BIG (-1e30f)

static __device__ float g_Q[(size_t)BTR * EMBD];
static __device__ float g_K[(size_t)BTR * EMBD];
static __device__ float g_V[(size_t)BTR * EMBD];
static __device__ float g_O[(size_t)BTR * EMBD];
static __device__ float g_W[(size_t)Bb * Hh * Tt * Tt];

// ===========================================================================
// helpers
// ===========================================================================
__device__ __forceinline__ uint32_t smem_u32(const void* p) {
    uint32_t a;
    asm("{ .reg .u64 t; cvta.to.shared.u64 t, %1; cvt.u32.u64 %0, t; }" : "=r"(a) : "l"(p));
    return a;
}
__device__ __forceinline__ void ldsm4(uint32_t addr, uint32_t& r0, uint32_t& r1,
                                      uint32_t& r2, uint32_t& r3) {
    asm volatile("ldmatrix.sync.aligned.m8n8.x4.shared.b16 {%0,%1,%2,%3}, [%4];"
                 : "=r"(r0), "=r"(r1), "=r"(r2), "=r"(r3) : "r"(addr));
}
__device__ __forceinline__ void ldsm4t(uint32_t addr, uint32_t& r0, uint32_t& r1,
                                       uint32_t& r2, uint32_t& r3) {
    asm volatile("ldmatrix.sync.aligned.m8n8.x4.trans.shared.b16 {%0,%1,%2,%3}, [%4];"
                 : "=r"(r0), "=r"(r1), "=r"(r2), "=r"(r3) : "r"(addr));
}
__device__ __forceinline__ void mma_bf16(float (&d)[4], const uint32_t (&a)[4],
                                         uint32_t b0, uint32_t b1) {
    asm volatile("mma.sync.aligned.m16n8k16.row.col.f32.bf16.bf16.f32 "
                 "{%0,%1,%2,%3},{%4,%5,%6,%7},{%8,%9},{%0,%1,%2,%3};"
                 : "+f"(d[0]), "+f"(d[1]), "+f"(d[2]), "+f"(d[3])
                 : "r"(a[0]), "r"(a[1]), "r"(a[2]), "r"(a[3]), "r"(b0), "r"(b1));
}
__device__ __forceinline__ void cvt_hilo(float4 v, uint2& hi, uint2& lo) {
    __nv_bfloat162 h0 = __floats2bfloat162_rn(v.x, v.y);
    __nv_bfloat162 h1 = __floats2bfloat162_rn(v.z, v.w);
    float rx = v.x - __bfloat162float(h0.x);
    float ry = v.y - __bfloat162float(h0.y);
    float rz = v.z - __bfloat162float(h1.x);
    float rw = v.w - __bfloat162float(h1.y);
    __nv_bfloat162 l0 = __floats2bfloat162_rn(rx, ry);
    __nv_bfloat162 l1 = __floats2bfloat162_rn(rz, rw);
    hi = make_uint2(*(uint32_t*)&h0, *(uint32_t*)&h1);
    lo = make_uint2(*(uint32_t*)&l0, *(uint32_t*)&l1);
}
__device__ __forceinline__ void pack2(float x, float y, uint32_t& h, uint32_t& l) {
    __nv_bfloat162 hh = __floats2bfloat162_rn(x, y);
    float rx = x - __bfloat162float(hh.x);
    float ry = y - __bfloat162float(hh.y);
    __nv_bfloat162 ll = __floats2bfloat162_rn(rx, ry);
    h = *(uint32_t*)&hh;
    l = *(uint32_t*)&ll;
}

// ===========================================================================
// NT GEMM (C = A * B^T), 128x128 block tile, BK=32, 512 threads / 16 warps
// (4M x 4N, warp tile 32x32), bf16 hi/lo 3-pass, fp32 in/out.
// ===========================================================================
#define STR_K  40
#define A_HI_O 0
#define A_LO_O 10240
#define B_HI_O 20480
#define B_LO_O 30720
#define STAGE_NT 40960

__device__ __forceinline__ void nt_body(const float* __restrict__ Ab,
                                        const float* __restrict__ Bp,
                                        float* __restrict__ Cb, char* sm)
{
    const int tid = threadIdx.x, lane = tid & 31, wid = tid >> 5;
    const int m0 = blockIdx.y * 128;
    const int n0 = blockIdx.x * 128;
    const int NC = EMBD / 32;

    float acc[2][4][4] = {};
    float4 la[2], lb[2];

    // prologue: stage 0
    {
        #pragma unroll
        for (int i = 0; i < 2; i++) {
            int seg = tid + i * 512, row = seg >> 3, c4 = (seg & 7) << 2;
            la[i] = *(const float4*)&Ab[(size_t)(m0 + row) * EMBD + c4];
            lb[i] = *(const float4*)&Bp[(size_t)(n0 + row) * EMBD + c4];
        }
        #pragma unroll
        for (int i = 0; i < 2; i++) {
            int seg = tid + i * 512, row = seg >> 3, c4 = (seg & 7) << 2;
            uint2 h, l;
            cvt_hilo(la[i], h, l);
            uint32_t off = (uint32_t)(row * STR_K + c4) * 2;
            *(uint2*)(sm + A_HI_O + off) = h;
            *(uint2*)(sm + A_LO_O + off) = l;
            cvt_hilo(lb[i], h, l);
            *(uint2*)(sm + B_HI_O + off) = h;
            *(uint2*)(sm + B_LO_O + off) = l;
        }
    }
    __syncthreads();

    const int wm = wid >> 2, wn = wid & 3;
    const int arow = lane & 15, acol8 = (lane >> 4) << 3;
    const int brow = (lane & 7) + ((lane >> 4) << 3), bcol8 = ((lane >> 3) & 1) << 3;
    const uint32_t sb0 = smem_u32(sm);

    for (int c = 0; c < NC; c++) {
        if (c + 1 < NC) {
            int k0n = (c + 1) * 32;
            #pragma unroll
            for (int i = 0; i < 2; i++) {
                int seg = tid + i * 512, row = seg >> 3, c4 = (seg & 7) << 2;
                la[i] = *(const float4*)&Ab[(size_t)(m0 + row) * EMBD + k0n + c4];
                lb[i] = *(const float4*)&Bp[(size_t)(n0 + row) * EMBD + k0n + c4];
            }
        }
        const uint32_t sbase = sb0 + (c & 1) * STAGE_NT;
        #pragma unroll
        for (int ks = 0; ks < 2; ks++) {
            const int k0 = ks * 16;
            uint32_t ah[2][4], al[2][4];
            #pragma unroll
            for (int mt = 0; mt < 2; mt++) {
                int r = wm * 32 + mt * 16 + arow;
                uint32_t ad = sbase + A_HI_O + (r * STR_K + k0 + acol8) * 2;
                ldsm4(ad, ah[mt][0], ah[mt][1], ah[mt][2], ah[mt][3]);
                ldsm4(ad + (A_LO_O - A_HI_O), al[mt][0], al[mt][1], al[mt][2], al[mt][3]);
            }
            uint32_t bh[4][2], bl[4][2];
            #pragma unroll
            for (int bt = 0; bt < 2; bt++) {
                int r = wn * 32 + bt * 16 + brow;
                uint32_t bd = sbase + B_HI_O + (r * STR_K + k0 + bcol8) * 2;
                ldsm4(bd, bh[2 * bt][0], bh[2 * bt][1], bh[2 * bt + 1][0], bh[2 * bt + 1][1]);
                ldsm4(bd + (B_LO_O - B_HI_O),
                      bl[2 * bt][0], bl[2 * bt][1], bl[2 * bt + 1][0], bl[2 * bt + 1][1]);
            }
            #pragma unroll
            for (int mt = 0; mt < 2; mt++)
                #pragma unroll
                for (int nt = 0; nt < 4; nt++) {
                    mma_bf16(acc[mt][nt], ah[mt], bh[nt][0], bh[nt][1]);
                    mma_bf16(acc[mt][nt], ah[mt], bl[nt][0], bl[nt][1]);
                    mma_bf16(acc[mt][nt], al[mt], bh[nt][0], bh[nt][1]);
                }
        }
        if (c + 1 < NC) {
            char* dst = sm + ((c + 1) & 1) * STAGE_NT;
            #pragma unroll
            for (int i = 0; i < 2; i++) {
                int seg = tid + i * 512, row = seg >> 3, c4 = (seg & 7) << 2;
                uint2 h, l;
                cvt_hilo(la[i], h, l);
                uint32_t off = (uint32_t)(row * STR_K + c4) * 2;
                *(uint2*)(dst + A_HI_O + off) = h;
                *(uint2*)(dst + A_LO_O + off) = l;
                cvt_hilo(lb[i], h, l);
                *(uint2*)(dst + B_HI_O + off) = h;
                *(uint2*)(dst + B_LO_O + off) = l;
            }
        }
        __syncthreads();
    }

    const int rofs = lane >> 2, cofs = (lane & 3) * 2;
    #pragma unroll
    for (int mt = 0; mt < 2; mt++)
        #pragma unroll
        for (int nt = 0; nt < 4; nt++) {
            int m = m0 + wm * 32 + mt * 16 + rofs;
            int n = n0 + wn * 32 + nt * 8 + cofs;
            *(float2*)&Cb[(size_t)m * EMBD + n] =
                make_float2(acc[mt][nt][0], acc[mt][nt][1]);
            *(float2*)&Cb[(size_t)(m + 8) * EMBD + n] =
                make_float2(acc[mt][nt][2], acc[mt][nt][3]);
        }
}

__global__ void __launch_bounds__(512)
mma_qkv(const float* __restrict__ x, const float* __restrict__ ctx,
        const float* __restrict__ WQ, const float* __restrict__ WK,
        const float* __restrict__ WV,
        float* __restrict__ qp, float* __restrict__ kp, float* __restrict__ vp)
{
    extern __shared__ __align__(16) char sm[];
    const int z = blockIdx.z;
    const float* Ab = (z == 0) ? x : ctx;
    const float* Bp = (z == 0) ? WQ : ((z == 1) ? WK : WV);
    float* Cb = (z == 0) ? qp : ((z == 1) ? kp : vp);
    nt_body(Ab, Bp, Cb, sm);
}

__global__ void __launch_bounds__(512)
mma_out(const float* __restrict__ A, const float* __restrict__ W,
        float* __restrict__ C)
{
    extern __shared__ __align__(16) char sm[];
    nt_body(A, W, C, sm);
}

// ===========================================================================
// Fused attention (R5 structure): phase 1 stats with HI-ONLY scores,
// phase 2 full bf16x3 scores + weights + AV.
// ===========================================================================
#define QSTR  72
#define F_LO  18432
#define FQ    0
#define FK0   36864
#define FK1   73728
#define FV0   110592
#define FV1   147456
#define FSMEM 184320

__device__ __forceinline__ void fill64(const float* __restrict__ src, char* dst, int tid) {
    #pragma unroll
    for (int i = 0; i < 8; i++) {
        int seg = tid + i * 256, row = seg >> 4, c4 = (seg & 15) << 2;
        float4 v = *(const float4*)&src[(size_t)row * EMBD + c4];
        uint2 h, l;
        cvt_hilo(v, h, l);
        uint32_t off = (uint32_t)(row * QSTR + c4) * 2;
        *(uint2*)(dst + off) = h;
        *(uint2*)(dst + F_LO + off) = l;
    }
}

// hi-only fill for phase-1 K tiles
__device__ __forceinline__ void fill64_hi(const float* __restrict__ src, char* dst, int tid) {
    #pragma unroll
    for (int i = 0; i < 8; i++) {
        int seg = tid + i * 256, row = seg >> 4, c4 = (seg & 15) << 2;
        float4 v = *(const float4*)&src[(size_t)row * EMBD + c4];
        __nv_bfloat162 h0 = __floats2bfloat162_rn(v.x, v.y);
        __nv_bfloat162 h1 = __floats2bfloat162_rn(v.z, v.w);
        uint32_t off = (uint32_t)(row * QSTR + c4) * 2;
        *(uint2*)(dst + off) = make_uint2(*(uint32_t*)&h0, *(uint32_t*)&h1);
    }
}

// full-precision score tile (bf16x3)
#define SCORE_TILE(accv, smK)                                                    \
    do {                                                                          \
        _Pragma("unroll")                                                         \
        for (int ks = 0; ks < 4; ks++) {                                          \
            uint32_t bh[16][2], bl[16][2];                                        \
            _Pragma("unroll")                                                     \
            for (int bp = 0; bp < 8; bp++) {                                      \
                uint32_t bd = (smK) + ((bp * 16 + brow) * QSTR + ks * 16 + bcol8) * 2; \
                ldsm4(bd, bh[2 * bp][0], bh[2 * bp][1], bh[2 * bp + 1][0], bh[2 * bp + 1][1]); \
                ldsm4(bd + F_LO, bl[2 * bp][0], bl[2 * bp][1], bl[2 * bp + 1][0], bl[2 * bp + 1][1]); \
            }                                                                     \
            _Pragma("unroll")                                                     \
            for (int nt = 0; nt < 16; nt++) {                                     \
                mma_bf16(accv[nt], qh[ks], bh[nt][0], bh[nt][1]);                 \
                mma_bf16(accv[nt], qh[ks], bl[nt][0], bl[nt][1]);                 \
                mma_bf16(accv[nt], ql[ks], bh[nt][0], bh[nt][1]);                 \
            }                                                                     \
        }                                                                         \
    } while (0)

// hi-only score tile for the stats phase
#define SCORE_TILE_HI(accv, smK)                                                 \
    do {                                                                          \
        _Pragma("unroll")                                                         \
        for (int ks = 0; ks < 4; ks++) {                                          \
            uint32_t bh[16][2];                                                   \
            _Pragma("unroll")                                                     \
            for (int bp = 0; bp < 8; bp++) {                                      \
                uint32_t bd = (smK) + ((bp * 16 + brow) * QSTR + ks * 16 + bcol8) * 2; \
                ldsm4(bd, bh[2 * bp][0], bh[2 * bp][1], bh[2 * bp + 1][0], bh[2 * bp + 1][1]); \
            }                                                                     \
            _Pragma("unroll")                                                     \
            for (int nt = 0; nt < 16; nt++)                                       \
                mma_bf16(accv[nt], qh[ks], bh[nt][0], bh[nt][1]);                 \
        }                                                                         \
    } while (0)

__global__ void __launch_bounds__(256)
fused_attn(const float* __restrict__ Q, const float* __restrict__ K,
           const float* __restrict__ V, const int* __restrict__ mask,
           float* __restrict__ Wt, float* __restrict__ O, int write_w)
{
    extern __shared__ __align__(16) char sm[];
    const uint32_t sb = smem_u32(sm);
    const int tid = threadIdx.x, lane = tid & 31, w = tid >> 5;
    const int z = blockIdx.y, b = z >> 4, h = z & 15;
    const int m0 = blockIdx.x * 128;

    const float* Qb = Q + (size_t)b * Tt * EMBD + h * HEAD;
    const float* Kb = K + (size_t)b * Tt * EMBD + h * HEAD;
    const float* Vb = V + (size_t)b * Tt * EMBD + h * HEAD;
    const int* mb = mask + (size_t)b * Tt * Tt + (size_t)m0 * Tt;

    const int g = lane >> 2, i2 = (lane & 3) << 1;
    const int arow = lane & 15, acol8 = (lane >> 4) << 3;
    const int brow = (lane & 7) + ((lane >> 4) << 3), bcol8 = ((lane >> 3) & 1) << 3;
    const int tbrow = (lane & 7) + (((lane >> 3) & 1) << 3), tbcol8 = (lane >> 4) << 3;

    fill64(Qb + (size_t)m0 * EMBD, sm + FQ, tid);
    fill64_hi(Kb, sm + FK0, tid);
    __syncthreads();

    uint32_t qh[4][4], ql[4][4];
    #pragma unroll
    for (int ks = 0; ks < 4; ks++) {
        uint32_t ad = sb + FQ + ((w * 16 + arow) * QSTR + ks * 16 + acol8) * 2;
        ldsm4(ad, qh[ks][0], qh[ks][1], qh[ks][2], qh[ks][3]);
        ldsm4(ad + F_LO, ql[ks][0], ql[ks][1], ql[ks][2], ql[ks][3]);
    }

    const int trow = w * 16 + g;

    // ---------------- phase 1: stats (hi-only scores) ----------------
    float rm0 = -3.0e38f, rm1 = -3.0e38f, rs0 = 0.f, rs1 = 0.f;
    for (int st = 0; st < 8; st++) {
        if (st < 7) fill64_hi(Kb + (size_t)(st + 1) * 128 * EMBD,
                              sm + (((st + 1) & 1) ? FK1 : FK0), tid);
        float acc[16][4] = {};
        const uint32_t smK = sb + ((st & 1) ? FK1 : FK0);
        SCORE_TILE_HI(acc, smK);

        const int* mr0 = mb + (size_t)trow * Tt + st * 128;
        const int* mr1 = mr0 + 8 * Tt;
        #pragma unroll
        for (int nt = 0; nt < 16; nt++) {
            int2 k0 = *(const int2*)&mr0[nt * 8 + i2];
            int2 k1 = *(const int2*)&mr1[nt * 8 + i2];
            acc[nt][0] = k0.x ? NEG_BIG : acc[nt][0] * 0.125f;
            acc[nt][1] = k0.y ? NEG_BIG : acc[nt][1] * 0.125f;
            acc[nt][2] = k1.x ? NEG_BIG : acc[nt][2] * 0.125f;
            acc[nt][3] = k1.y ? NEG_BIG : acc[nt][3] * 0.125f;
        }
        float t0 = -3.0e38f, t1 = -3.0e38f;
        #pragma unroll
        for (int nt = 0; nt < 16; nt++) {
            t0 = fmaxf(t0, fmaxf(acc[nt][0], acc[nt][1]));
            t1 = fmaxf(t1, fmaxf(acc[nt][2], acc[nt][3]));
        }
        t0 = fmaxf(t0, __shfl_xor_sync(0xffffffffu, t0, 1));
        t0 = fmaxf(t0, __shfl_xor_sync(0xffffffffu, t0, 2));
        t1 = fmaxf(t1, __shfl_xor_sync(0xffffffffu, t1, 1));
        t1 = fmaxf(t1, __shfl_xor_sync(0xffffffffu, t1, 2));
        float nm0 = fmaxf(rm0, t0), nm1 = fmaxf(rm1, t1);
        float s0 = 0.f, s1 = 0.f;
        #pragma unroll
        for (int nt = 0; nt < 16; nt++) {
            s0 += __expf(acc[nt][0] - nm0) + __expf(acc[nt][1] - nm0);
            s1 += __expf(acc[nt][2] - nm1) + __expf(acc[nt][3] - nm1);
        }
        s0 += __shfl_xor_sync(0xffffffffu, s0, 1);
        s0 += __shfl_xor_sync(0xffffffffu, s0, 2);
        s1 += __shfl_xor_sync(0xffffffffu, s1, 1);
        s1 += __shfl_xor_sync(0xffffffffu, s1, 2);
        rs0 = rs0 * __expf(rm0 - nm0) + s0;  rm0 = nm0;
        rs1 = rs1 * __expf(rm1 - nm1) + s1;  rm1 = nm1;
        __syncthreads();
    }
    const float inv0 = (rm0 <= -1e29f) ? 0.f : 1.f / rs0;
    const float inv1 = (rm1 <= -1e29f) ? 0.f : 1.f / rs1;

    // ---------------- phase 2: weights + AV (full precision) ----------------
    fill64(Kb, sm + FK0, tid);
    fill64(Vb, sm + FV0, tid);
    __syncthreads();

    float acco[8][4] = {};
    float* wrow0 = Wt + (size_t)z * Tt * Tt + (size_t)(m0 + trow) * Tt;
    float* wrow1 = wrow0 + 8 * Tt;

    for (int st = 0; st < 8; st++) {
        if (st < 7) {
            const int nb = (st + 1) & 1;
            fill64(Kb + (size_t)(st + 1) * 128 * EMBD, sm + (nb ? FK1 : FK0), tid);
            fill64(Vb + (size_t)(st + 1) * 128 * EMBD, sm + (nb ? FV1 : FV0), tid);
        }
        float acc[16][4] = {};
        const uint32_t smK = sb + ((st & 1) ? FK1 : FK0);
        const uint32_t smV = sb + ((st & 1) ? FV1 : FV0);
        SCORE_TILE(acc, smK);

        const int* mr0 = mb + (size_t)trow * Tt + st * 128;
        const int* mr1 = mr0 + 8 * Tt;
        #pragma unroll
        for (int nt = 0; nt < 16; nt++) {
            int2 k0 = *(const int2*)&mr0[nt * 8 + i2];
            int2 k1 = *(const int2*)&mr1[nt * 8 + i2];
            float v0 = k0.x ? NEG_BIG : acc[nt][0] * 0.125f;
            float v1 = k0.y ? NEG_BIG : acc[nt][1] * 0.125f;
            float v2 = k1.x ? NEG_BIG : acc[nt][2] * 0.125f;
            float v3 = k1.y ? NEG_BIG : acc[nt][3] * 0.125f;
            acc[nt][0] = __expf(v0 - rm0) * inv0;
            acc[nt][1] = __expf(v1 - rm0) * inv0;
            acc[nt][2] = __expf(v2 - rm1) * inv1;
            acc[nt][3] = __expf(v3 - rm1) * inv1;
        }
        if (write_w) {
            #pragma unroll
            for (int nt = 0; nt < 16; nt++) {
                *(float2*)&wrow0[st * 128 + nt * 8 + i2] = make_float2(acc[nt][0], acc[nt][1]);
                *(float2*)&wrow1[st * 128 + nt * 8 + i2] = make_float2(acc[nt][2], acc[nt][3]);
            }
        }
        #pragma unroll
        for (int j = 0; j < 8; j++) {
            uint32_t ph[4], pl[4];
            pack2(acc[2 * j][0],     acc[2 * j][1],     ph[0], pl[0]);
            pack2(acc[2 * j][2],     acc[2 * j][3],     ph[1], pl[1]);
            pack2(acc[2 * j + 1][0], acc[2 * j + 1][1], ph[2], pl[2]);
            pack2(acc[2 * j + 1][2], acc[2 * j + 1][3], ph[3], pl[3]);
            uint32_t vh[8][2], vl[8][2];
            #pragma unroll
            for (int bt = 0; bt < 4; bt++) {
                uint32_t vd = smV + ((j * 16 + tbrow) * QSTR + bt * 16 + tbcol8) * 2;
                ldsm4t(vd, vh[2 * bt][0], vh[2 * bt][1], vh[2 * bt + 1][0], vh[2 * bt + 1][1]);
                ldsm4t(vd + F_LO, vl[2 * bt][0], vl[2 * bt][1], vl[2 * bt + 1][0], vl[2 * bt + 1][1]);
            }
            #pragma unroll
            for (int ntv = 0; ntv < 8; ntv++) {
                mma_bf16(acco[ntv], ph, vh[ntv][0], vh[ntv][1]);
                mma_bf16(acco[ntv], ph, vl[ntv][0], vl[ntv][1]);
                mma_bf16(acco[ntv], pl, vh[ntv][0], vh[ntv][1]);
            }
        }
        __syncthreads();
    }

    float* Ob = O + (size_t)b * Tt * EMBD + h * HEAD + (size_t)(m0 + trow) * EMBD;
    #pragma unroll
    for (int ntv = 0; ntv < 8; ntv++) {
        *(float2*)&Ob[ntv * 8 + i2] = make_float2(acco[ntv][0], acco[ntv][1]);
        *(float2*)&Ob[8 * EMBD + ntv * 8 + i2] = make_float2(acco[ntv][2], acco[ntv][3]);
    }
}

// ===========================================================================
extern "C" void kernel_launch(void* const* d_in, const int* in_sizes, int n_in,
                              void* d_out, int out_size)
{
    const float* x    = (const float*)d_in[0];
    const float* ctx  = (const float*)d_in[1];
    const int*   mask = (const int*)d_in[2];
    const float* WQ = (const float*)d_in[3];
    const float* WK = (const float*)d_in[4];
    const float* WV = (const float*)d_in[5];
    const float* WO = (const float*)d_in[6];
    float* out = (float*)d_out;

    float *qp, *kp, *vp, *op;
    cudaGetSymbolAddress((void**)&qp, g_Q);
    cudaGetSymbolAddress((void**)&kp, g_K);
    cudaGetSymbolAddress((void**)&vp, g_V);
    cudaGetSymbolAddress((void**)&op, g_O);

    const size_t merged_elems = (size_t)BTR * EMBD;
    const size_t weight_elems = (size_t)Bb * Hh * Tt * Tt;
    const int write_w = ((size_t)out_size >= merged_elems + weight_elems) ? 1 : 0;
    float* wt;
    if (write_w) {
        wt = out + merged_elems;
    } else {
        cudaGetSymbolAddress((void**)&wt, g_W);
    }

    const int SMEM_NT = 2 * STAGE_NT;   // 80 KB
    cudaFuncSetAttribute(mma_qkv, cudaFuncAttributeMaxDynamicSharedMemorySize, SMEM_NT);
    cudaFuncSetAttribute(mma_out, cudaFuncAttributeMaxDynamicSharedMemorySize, SMEM_NT);
    cudaFuncSetAttribute(fused_attn, cudaFuncAttributeMaxDynamicSharedMemorySize, FSMEM);

    // Q/K/V projections, 512 threads (16 warps) per CTA
    dim3 gqkv(EMBD / 128, BTR / 128, 3);
    mma_qkv<<<gqkv, 512, SMEM_NT>>>(x, ctx, WQ, WK, WV, qp, kp, vp);

    // fused scores+softmax+weights+AV
    dim3 gf(Tt / 128, Bb * Hh);
    fused_attn<<<gf, 256, FSMEM>>>(qp, kp, vp, mask, wt, op, write_w);

    // output projection
    dim3 gout(EMBD / 128, BTR / 128);
    mma_out<<<gout, 512, SMEM_NT>>>(op, WO, out);
}